// round 2
// baseline (speedup 1.0000x reference)
#include <cuda_runtime.h>

#define NNODES  100000
#define NEDGES  1600000
#define NGRAPHS 64
#define DIM     128
#define NCLS    10

// ---------------- persistent device scratch (no allocations allowed) ----------------
__device__ int   g_idx64;                 // 1 if indices are int64, 0 if int32
__device__ int   g_deg_out[NNODES];
__device__ int   g_deg_in[NNODES];
__device__ int   g_fill[NNODES];
__device__ int   g_rowptr[NNODES + 1];
__device__ int   g_csr[NEDGES];           // src indices grouped by dst (CSR by dst)
__device__ float g_rs_out[NNODES];
__device__ float g_rs_in[NNODES];
__device__ __align__(16) float g_bufA[(size_t)NNODES * DIM];  // GEMM outputs
__device__ __align__(16) float g_bufB[(size_t)NNODES * DIM];  // layer-1 activations (pre-scaled)
__device__ float g_gsum[NGRAPHS * DIM];
__device__ int   g_gcnt[NGRAPHS];

// ---------------- helpers ----------------
__device__ __forceinline__ int ldidx(const void* p, int i, bool w64) {
    if (w64) return (int)__ldg(((const long long*)p) + i);
    return __ldg(((const int*)p) + i);
}

// ---------------- 1. dtype detection (parallel: 256 independent loads) ----------------
// int64 little-endian values < 2^31 have all-zero high words. For int32 data the
// "high words" are random indices in [0,100000): P(all 256 zero) ~ 0.
__global__ void k_detect(const void* src) {
    __shared__ int any_nonzero;
    if (threadIdx.x == 0) any_nonzero = 0;
    __syncthreads();
    const unsigned int* p = (const unsigned int*)src;
    unsigned int v = p[2 * threadIdx.x + 1];
    if (v != 0u) atomicOr(&any_nonzero, 1);
    __syncthreads();
    if (threadIdx.x == 0) g_idx64 = (any_nonzero == 0) ? 1 : 0;
}

// ---------------- 2. zero scratch ----------------
__global__ void k_zero() {
    int i = blockIdx.x * blockDim.x + threadIdx.x;
    int stride = gridDim.x * blockDim.x;
    for (int j = i; j < NNODES; j += stride) {
        g_deg_out[j] = 0;
        g_deg_in[j]  = 0;
        g_fill[j]    = 0;
    }
    for (int j = i; j < NGRAPHS * DIM; j += stride) g_gsum[j] = 0.0f;
    if (i < NGRAPHS) g_gcnt[i] = 0;
}

// ---------------- 3. degree + graph-count histograms ----------------
__global__ void k_degrees(const void* src, const void* dst, const void* gids) {
    bool w64 = (g_idx64 != 0);
    int i0 = blockIdx.x * blockDim.x + threadIdx.x;
    int stride = gridDim.x * blockDim.x;
    for (int i = i0; i < NEDGES; i += stride) {
        int s = ldidx(src, i, w64);
        int d = ldidx(dst, i, w64);
        atomicAdd(&g_deg_out[s], 1);
        atomicAdd(&g_deg_in[d], 1);
    }
    for (int i = i0; i < NNODES; i += stride) {
        int g = ldidx(gids, i, w64);
        atomicAdd(&g_gcnt[g], 1);
    }
}

// ---------------- 4. rsqrt of clipped degrees ----------------
__global__ void k_rsqrt() {
    int i = blockIdx.x * blockDim.x + threadIdx.x;
    if (i >= NNODES) return;
    g_rs_out[i] = rsqrtf((float)max(g_deg_out[i], 1));
    g_rs_in[i]  = rsqrtf((float)max(g_deg_in[i], 1));
}

// ---------------- 5. single-block exclusive scan of deg_in -> rowptr ----------------
__global__ void k_scan() {
    __shared__ int sums[1024];
    const int n = NNODES;
    const int CH = (n + 1023) / 1024;   // 98
    int tid = threadIdx.x;
    int beg = tid * CH;
    int end = min(beg + CH, n);
    int s = 0;
    for (int i = beg; i < end; i++) s += g_deg_in[i];
    sums[tid] = s;
    __syncthreads();
    for (int off = 1; off < 1024; off <<= 1) {
        int v = 0;
        if (tid >= off) v = sums[tid - off];
        __syncthreads();
        sums[tid] += v;
        __syncthreads();
    }
    int run = (tid > 0) ? sums[tid - 1] : 0;
    for (int i = beg; i < end; i++) {
        g_rowptr[i] = run;
        run += g_deg_in[i];
    }
    if (tid == 1023) g_rowptr[n] = run;
}

// ---------------- 6. CSR scatter: edges grouped by dst ----------------
__global__ void k_scatter(const void* src, const void* dst) {
    bool w64 = (g_idx64 != 0);
    int i0 = blockIdx.x * blockDim.x + threadIdx.x;
    int stride = gridDim.x * blockDim.x;
    for (int e = i0; e < NEDGES; e += stride) {
        int d = ldidx(dst, e, w64);
        int s = ldidx(src, e, w64);
        int pos = g_rowptr[d] + atomicAdd(&g_fill[d], 1);
        g_csr[pos] = s;
    }
}

// ---------------- 7. SGEMM: C[M,128] = (scale ? diag(rs_out) : I) * A[M,128] @ W[128,128] ----------------
// Conflict-free LDS mapping: each thread owns rows {tr*4..+3, 64+tr*4..+3},
// cols {tc*4..+3, 64+tc*4..+3}. Register-prefetch pipeline over k-tiles.
template <int LAYER>
__global__ void __launch_bounds__(256) k_sgemm(const float* __restrict__ Aext,
                                              const float* __restrict__ W, int M) {
    __shared__ __align__(16) float As[16][132];  // transposed A tile, padded
    __shared__ __align__(16) float Bs[16][132];

    const float* __restrict__ A = (LAYER == 1) ? Aext : g_bufB;
    float* __restrict__ C = g_bufA;

    int tid = threadIdx.x;
    int blockM = blockIdx.x * 128;
    int tr = tid / 16;       // 0..15
    int tc = tid % 16;       // 0..15
    int aRow  = tid / 4;     // 0..63
    int aCol4 = tid % 4;     // 0..3
    int bRow  = tid / 32;    // 0..7
    int bCol4 = tid % 32;    // 0..31

    float acc[8][8];
#pragma unroll
    for (int i = 0; i < 8; i++)
#pragma unroll
        for (int j = 0; j < 8; j++) acc[i][j] = 0.0f;

    float4 aPre[2], bPre[2];
    float  aScale[2];

    // prefetch k-tile 0
#pragma unroll
    for (int r = 0; r < 2; r++) {
        int row = blockM + aRow + r * 64;
        aPre[r] = make_float4(0.f, 0.f, 0.f, 0.f);
        aScale[r] = 1.0f;
        if (row < M) {
            aPre[r] = *(const float4*)(A + (long)row * 128 + 0 + aCol4 * 4);
            if (LAYER == 1) aScale[r] = g_rs_out[row];
        }
        bPre[r] = *(const float4*)(W + (0 + bRow + r * 8) * 128 + bCol4 * 4);
    }

    for (int k0 = 0; k0 < 128; k0 += 16) {
        // commit prefetched tile to smem
#pragma unroll
        for (int r = 0; r < 2; r++) {
            float4 v = aPre[r];
            if (LAYER == 1) { v.x *= aScale[r]; v.y *= aScale[r]; v.z *= aScale[r]; v.w *= aScale[r]; }
            As[aCol4 * 4 + 0][aRow + r * 64] = v.x;
            As[aCol4 * 4 + 1][aRow + r * 64] = v.y;
            As[aCol4 * 4 + 2][aRow + r * 64] = v.z;
            As[aCol4 * 4 + 3][aRow + r * 64] = v.w;
            *(float4*)&Bs[bRow + r * 8][bCol4 * 4] = bPre[r];
        }
        __syncthreads();
        // prefetch next tile into registers (overlaps with FFMA below)
        if (k0 + 16 < 128) {
            int kn = k0 + 16;
#pragma unroll
            for (int r = 0; r < 2; r++) {
                int row = blockM + aRow + r * 64;
                aPre[r] = make_float4(0.f, 0.f, 0.f, 0.f);
                if (row < M) aPre[r] = *(const float4*)(A + (long)row * 128 + kn + aCol4 * 4);
                bPre[r] = *(const float4*)(W + (kn + bRow + r * 8) * 128 + bCol4 * 4);
            }
        }
#pragma unroll
        for (int k = 0; k < 16; k++) {
            float regM[8], regN[8];
            float4 m0 = *(const float4*)&As[k][tr * 4];
            float4 m1 = *(const float4*)&As[k][64 + tr * 4];
            regM[0] = m0.x; regM[1] = m0.y; regM[2] = m0.z; regM[3] = m0.w;
            regM[4] = m1.x; regM[5] = m1.y; regM[6] = m1.z; regM[7] = m1.w;
            float4 n0 = *(const float4*)&Bs[k][tc * 4];
            float4 n1 = *(const float4*)&Bs[k][64 + tc * 4];
            regN[0] = n0.x; regN[1] = n0.y; regN[2] = n0.z; regN[3] = n0.w;
            regN[4] = n1.x; regN[5] = n1.y; regN[6] = n1.z; regN[7] = n1.w;
#pragma unroll
            for (int i = 0; i < 8; i++)
#pragma unroll
                for (int j = 0; j < 8; j++) acc[i][j] = fmaf(regM[i], regN[j], acc[i][j]);
        }
        __syncthreads();
    }
    // store: rows {tr*4+i, 64+tr*4+i}, cols {tc*4.., 64+tc*4..}
#pragma unroll
    for (int half = 0; half < 2; half++) {
#pragma unroll
        for (int i = 0; i < 4; i++) {
            int row = blockM + half * 64 + tr * 4 + i;
            int ai = half * 4 + i;
            if (row < M) {
                float4 o0 = make_float4(acc[ai][0], acc[ai][1], acc[ai][2], acc[ai][3]);
                float4 o1 = make_float4(acc[ai][4], acc[ai][5], acc[ai][6], acc[ai][7]);
                *(float4*)(C + (long)row * 128 + tc * 4)      = o0;
                *(float4*)(C + (long)row * 128 + 64 + tc * 4) = o1;
            }
        }
    }
}

// ---------------- 8. SpMM (warp per dst row, 8-wide MLP, dual accumulators) ----------------
template <bool FINAL>
__global__ void __launch_bounds__(256) k_spmm(const float* __restrict__ bias,
                                              const void* __restrict__ gids) {
    int warp = (blockIdx.x * blockDim.x + threadIdx.x) >> 5;
    if (warp >= NNODES) return;
    int lane = threadIdx.x & 31;
    int beg = g_rowptr[warp], end = g_rowptr[warp + 1];
    const float* __restrict__ T = g_bufA;
    float4 acc0 = make_float4(0.f, 0.f, 0.f, 0.f);
    float4 acc1 = make_float4(0.f, 0.f, 0.f, 0.f);
    int e = beg;
    for (; e + 8 <= end; e += 8) {
        int s0 = g_csr[e],     s1 = g_csr[e + 1], s2 = g_csr[e + 2], s3 = g_csr[e + 3];
        int s4 = g_csr[e + 4], s5 = g_csr[e + 5], s6 = g_csr[e + 6], s7 = g_csr[e + 7];
        float4 v0 = __ldg((const float4*)(T + (long)s0 * 128 + lane * 4));
        float4 v1 = __ldg((const float4*)(T + (long)s1 * 128 + lane * 4));
        float4 v2 = __ldg((const float4*)(T + (long)s2 * 128 + lane * 4));
        float4 v3 = __ldg((const float4*)(T + (long)s3 * 128 + lane * 4));
        float4 v4 = __ldg((const float4*)(T + (long)s4 * 128 + lane * 4));
        float4 v5 = __ldg((const float4*)(T + (long)s5 * 128 + lane * 4));
        float4 v6 = __ldg((const float4*)(T + (long)s6 * 128 + lane * 4));
        float4 v7 = __ldg((const float4*)(T + (long)s7 * 128 + lane * 4));
        acc0.x += (v0.x + v1.x) + (v2.x + v3.x);
        acc0.y += (v0.y + v1.y) + (v2.y + v3.y);
        acc0.z += (v0.z + v1.z) + (v2.z + v3.z);
        acc0.w += (v0.w + v1.w) + (v2.w + v3.w);
        acc1.x += (v4.x + v5.x) + (v6.x + v7.x);
        acc1.y += (v4.y + v5.y) + (v6.y + v7.y);
        acc1.z += (v4.z + v5.z) + (v6.z + v7.z);
        acc1.w += (v4.w + v5.w) + (v6.w + v7.w);
    }
    for (; e + 4 <= end; e += 4) {
        int s0 = g_csr[e], s1 = g_csr[e + 1], s2 = g_csr[e + 2], s3 = g_csr[e + 3];
        float4 v0 = __ldg((const float4*)(T + (long)s0 * 128 + lane * 4));
        float4 v1 = __ldg((const float4*)(T + (long)s1 * 128 + lane * 4));
        float4 v2 = __ldg((const float4*)(T + (long)s2 * 128 + lane * 4));
        float4 v3 = __ldg((const float4*)(T + (long)s3 * 128 + lane * 4));
        acc0.x += (v0.x + v1.x) + (v2.x + v3.x);
        acc0.y += (v0.y + v1.y) + (v2.y + v3.y);
        acc0.z += (v0.z + v1.z) + (v2.z + v3.z);
        acc0.w += (v0.w + v1.w) + (v2.w + v3.w);
    }
    for (; e < end; e++) {
        int s = g_csr[e];
        float4 v = __ldg((const float4*)(T + (long)s * 128 + lane * 4));
        acc1.x += v.x; acc1.y += v.y; acc1.z += v.z; acc1.w += v.w;
    }
    float4 acc = make_float4(acc0.x + acc1.x, acc0.y + acc1.y,
                             acc0.z + acc1.z, acc0.w + acc1.w);
    float ri = g_rs_in[warp];
    float4 b = *(const float4*)(bias + lane * 4);
    if (!FINAL) {
        float ro = g_rs_out[warp];
        float4 o;
        o.x = fmaxf(fmaf(acc.x, ri, b.x), 0.f) * ro;
        o.y = fmaxf(fmaf(acc.y, ri, b.y), 0.f) * ro;
        o.z = fmaxf(fmaf(acc.z, ri, b.z), 0.f) * ro;
        o.w = fmaxf(fmaf(acc.w, ri, b.w), 0.f) * ro;
        *(float4*)(g_bufB + (long)warp * 128 + lane * 4) = o;
    } else {
        float4 o;
        o.x = fmaxf(fmaf(acc.x, ri, b.x), 0.f);
        o.y = fmaxf(fmaf(acc.y, ri, b.y), 0.f);
        o.z = fmaxf(fmaf(acc.z, ri, b.z), 0.f);
        o.w = fmaxf(fmaf(acc.w, ri, b.w), 0.f);
        bool w64 = (g_idx64 != 0);
        int g = ldidx(gids, warp, w64);
        float* dstp = g_gsum + g * 128 + lane * 4;
        atomicAdd(dstp + 0, o.x);
        atomicAdd(dstp + 1, o.y);
        atomicAdd(dstp + 2, o.z);
        atomicAdd(dstp + 3, o.w);
    }
}

// ---------------- 9. classifier head: logits = (gsum/cnt) @ Wc + bc ----------------
__global__ void k_final(const float* __restrict__ Wc, const float* __restrict__ bc,
                        float* __restrict__ out) {
    int t = threadIdx.x;
    if (t >= NGRAPHS * NCLS) return;
    int g = t / NCLS, c = t % NCLS;
    float s = 0.f;
#pragma unroll 8
    for (int k = 0; k < 128; k++) s = fmaf(g_gsum[g * 128 + k], Wc[k * NCLS + c], s);
    float cnt = (float)max(g_gcnt[g], 1);
    out[t] = s / cnt + bc[c];
}

// ---------------- launch ----------------
extern "C" void kernel_launch(void* const* d_in, const int* in_sizes, int n_in,
                              void* d_out, int out_size) {
    const float* h   = (const float*)d_in[0];
    const void*  src = d_in[1];
    const void*  dst = d_in[2];
    const void*  gid = d_in[3];
    const float* W1  = (const float*)d_in[4];
    const float* b1  = (const float*)d_in[5];
    const float* W2  = (const float*)d_in[6];
    const float* b2  = (const float*)d_in[7];
    const float* Wc  = (const float*)d_in[8];
    const float* bc  = (const float*)d_in[9];
    float* out = (float*)d_out;

    const int M = NNODES;

    k_detect<<<1, 256>>>(src);
    k_zero<<<512, 256>>>();
    k_degrees<<<1184, 256>>>(src, dst, gid);
    k_rsqrt<<<(NNODES + 255) / 256, 256>>>();
    k_scan<<<1, 1024>>>();
    k_scatter<<<1184, 256>>>(src, dst);

    int gemmGrid = (M + 127) / 128;
    int spmmGrid = (M * 32 + 255) / 256;

    k_sgemm<1><<<gemmGrid, 256>>>(h, W1, M);          // bufA = (h * rs_out) @ W1
    k_spmm<false><<<spmmGrid, 256>>>(b1, nullptr);    // bufB = relu(agg*rs_in + b1) * rs_out
    k_sgemm<2><<<gemmGrid, 256>>>(nullptr, W2, M);    // bufA = bufB @ W2
    k_spmm<true><<<spmmGrid, 256>>>(b2, gid);         // gsum += relu(agg*rs_in + b2)
    k_final<<<1, NGRAPHS * NCLS>>>(Wc, bc, out);
}

// round 3
// speedup vs baseline: 1.1257x; 1.1257x over previous
#include <cuda_runtime.h>

#define NNODES  100000
#define NEDGES  1600000
#define NGRAPHS 64
#define DIM     128
#define NCLS    10
#define SCAN_B  1024
#define NBLK    ((NNODES + SCAN_B - 1) / SCAN_B)   // 98

// ---------------- persistent device scratch (no allocations allowed) ----------------
__device__ int   g_idx64;                 // 1 if indices are int64, 0 if int32
__device__ int   g_deg_out[NNODES];
__device__ int   g_deg_in[NNODES];
__device__ int   g_fill[NNODES];          // scatter cursors (init = row starts)
__device__ int   g_rowptr[NNODES + 1];
__device__ int   g_csr[NEDGES];           // src indices grouped by dst (CSR by dst)
__device__ int   g_bsum[NBLK];
__device__ int   g_boff[128];
__device__ __align__(16) float g_bufA[(size_t)NNODES * DIM];  // GEMM outputs
__device__ __align__(16) float g_bufB[(size_t)NNODES * DIM];  // layer-1 activations (pre-scaled)
__device__ float g_gsum[NGRAPHS * DIM];
__device__ int   g_gcnt[NGRAPHS];

// ---------------- helpers ----------------
__device__ __forceinline__ int ldidx(const void* p, int i, bool w64) {
    if (w64) return (int)__ldg(((const long long*)p) + i);
    return __ldg(((const int*)p) + i);
}

// ---------------- 1. dtype detection (parallel) ----------------
__global__ void k_detect(const void* src) {
    __shared__ int any_nonzero;
    if (threadIdx.x == 0) any_nonzero = 0;
    __syncthreads();
    const unsigned int* p = (const unsigned int*)src;
    unsigned int v = p[2 * threadIdx.x + 1];
    if (v != 0u) atomicOr(&any_nonzero, 1);
    __syncthreads();
    if (threadIdx.x == 0) g_idx64 = (any_nonzero == 0) ? 1 : 0;
}

// ---------------- 2. zero scratch ----------------
__global__ void k_zero() {
    int i = blockIdx.x * blockDim.x + threadIdx.x;
    int stride = gridDim.x * blockDim.x;
    for (int j = i; j < NNODES; j += stride) {
        g_deg_out[j] = 0;
        g_deg_in[j]  = 0;
    }
    for (int j = i; j < NGRAPHS * DIM; j += stride) g_gsum[j] = 0.0f;
    if (i < NGRAPHS) g_gcnt[i] = 0;
}

// ---------------- 3. degree + graph-count histograms ----------------
__global__ void k_degrees(const void* src, const void* dst, const void* gids) {
    bool w64 = (g_idx64 != 0);
    int i0 = blockIdx.x * blockDim.x + threadIdx.x;
    int stride = gridDim.x * blockDim.x;
    for (int i = i0; i < NEDGES; i += stride) {
        int s = ldidx(src, i, w64);
        int d = ldidx(dst, i, w64);
        atomicAdd(&g_deg_out[s], 1);
        atomicAdd(&g_deg_in[d], 1);
    }
    for (int i = i0; i < NNODES; i += stride) {
        int g = ldidx(gids, i, w64);
        atomicAdd(&g_gcnt[g], 1);
    }
}

// ---------------- 4-6. coalesced 3-phase exclusive scan of deg_in ----------------
__global__ void __launch_bounds__(SCAN_B) k_scanA() {
    __shared__ int sh[SCAN_B];
    int tid = threadIdx.x;
    int i = blockIdx.x * SCAN_B + tid;
    int v = (i < NNODES) ? g_deg_in[i] : 0;
    sh[tid] = v;
    __syncthreads();
    for (int off = 1; off < SCAN_B; off <<= 1) {
        int t = (tid >= off) ? sh[tid - off] : 0;
        __syncthreads();
        sh[tid] += t;
        __syncthreads();
    }
    if (i < NNODES) g_rowptr[i] = sh[tid] - v;   // block-local exclusive prefix
    if (tid == SCAN_B - 1) g_bsum[blockIdx.x] = sh[tid];
}

__global__ void k_scanB() {
    __shared__ int sh[128];
    int tid = threadIdx.x;
    int v = (tid < NBLK) ? g_bsum[tid] : 0;
    sh[tid] = v;
    __syncthreads();
    for (int off = 1; off < 128; off <<= 1) {
        int t = (tid >= off) ? sh[tid - off] : 0;
        __syncthreads();
        sh[tid] += t;
        __syncthreads();
    }
    g_boff[tid] = sh[tid] - v;   // exclusive block offsets
}

__global__ void __launch_bounds__(SCAN_B) k_scanC() {
    int tid = threadIdx.x;
    int i = blockIdx.x * SCAN_B + tid;
    if (i < NNODES) {
        int r = g_rowptr[i] + g_boff[blockIdx.x];
        g_rowptr[i] = r;
        g_fill[i]   = r;          // scatter cursor starts at row begin
    }
    if (i == 0) g_rowptr[NNODES] = NEDGES;
}

// ---------------- 7. CSR scatter: edges grouped by dst ----------------
__global__ void k_scatter(const void* src, const void* dst) {
    bool w64 = (g_idx64 != 0);
    int i0 = blockIdx.x * blockDim.x + threadIdx.x;
    int stride = gridDim.x * blockDim.x;
    for (int e = i0; e < NEDGES; e += stride) {
        int d = ldidx(dst, e, w64);
        int s = ldidx(src, e, w64);
        int pos = atomicAdd(&g_fill[d], 1);
        g_csr[pos] = s;
    }
}

// ---------------- 8. SGEMM: C[M,128] = (scale ? diag(rsqrt(deg_out)) : I) * A @ W ----------------
template <int LAYER>
__global__ void __launch_bounds__(256) k_sgemm(const float* __restrict__ Aext,
                                              const float* __restrict__ W, int M) {
    __shared__ __align__(16) float As[16][132];  // transposed A tile, padded
    __shared__ __align__(16) float Bs[16][132];

    const float* __restrict__ A = (LAYER == 1) ? Aext : g_bufB;
    float* __restrict__ C = g_bufA;

    int tid = threadIdx.x;
    int blockM = blockIdx.x * 128;
    int tr = tid / 16;       // 0..15
    int tc = tid % 16;       // 0..15
    int aRow  = tid / 4;     // 0..63
    int aCol4 = tid % 4;     // 0..3
    int bRow  = tid / 32;    // 0..7
    int bCol4 = tid % 32;    // 0..31

    float acc[8][8];
#pragma unroll
    for (int i = 0; i < 8; i++)
#pragma unroll
        for (int j = 0; j < 8; j++) acc[i][j] = 0.0f;

    float4 aPre[2], bPre[2];
    float  aScale[2];

#pragma unroll
    for (int r = 0; r < 2; r++) {
        int row = blockM + aRow + r * 64;
        aPre[r] = make_float4(0.f, 0.f, 0.f, 0.f);
        aScale[r] = 1.0f;
        if (row < M) {
            aPre[r] = *(const float4*)(A + (long)row * 128 + 0 + aCol4 * 4);
            if (LAYER == 1) aScale[r] = rsqrtf((float)max(g_deg_out[row], 1));
        }
        bPre[r] = *(const float4*)(W + (0 + bRow + r * 8) * 128 + bCol4 * 4);
    }

    for (int k0 = 0; k0 < 128; k0 += 16) {
#pragma unroll
        for (int r = 0; r < 2; r++) {
            float4 v = aPre[r];
            if (LAYER == 1) { v.x *= aScale[r]; v.y *= aScale[r]; v.z *= aScale[r]; v.w *= aScale[r]; }
            As[aCol4 * 4 + 0][aRow + r * 64] = v.x;
            As[aCol4 * 4 + 1][aRow + r * 64] = v.y;
            As[aCol4 * 4 + 2][aRow + r * 64] = v.z;
            As[aCol4 * 4 + 3][aRow + r * 64] = v.w;
            *(float4*)&Bs[bRow + r * 8][bCol4 * 4] = bPre[r];
        }
        __syncthreads();
        if (k0 + 16 < 128) {
            int kn = k0 + 16;
#pragma unroll
            for (int r = 0; r < 2; r++) {
                int row = blockM + aRow + r * 64;
                aPre[r] = make_float4(0.f, 0.f, 0.f, 0.f);
                if (row < M) aPre[r] = *(const float4*)(A + (long)row * 128 + kn + aCol4 * 4);
                bPre[r] = *(const float4*)(W + (kn + bRow + r * 8) * 128 + bCol4 * 4);
            }
        }
#pragma unroll
        for (int k = 0; k < 16; k++) {
            float regM[8], regN[8];
            float4 m0 = *(const float4*)&As[k][tr * 4];
            float4 m1 = *(const float4*)&As[k][64 + tr * 4];
            regM[0] = m0.x; regM[1] = m0.y; regM[2] = m0.z; regM[3] = m0.w;
            regM[4] = m1.x; regM[5] = m1.y; regM[6] = m1.z; regM[7] = m1.w;
            float4 n0 = *(const float4*)&Bs[k][tc * 4];
            float4 n1 = *(const float4*)&Bs[k][64 + tc * 4];
            regN[0] = n0.x; regN[1] = n0.y; regN[2] = n0.z; regN[3] = n0.w;
            regN[4] = n1.x; regN[5] = n1.y; regN[6] = n1.z; regN[7] = n1.w;
#pragma unroll
            for (int i = 0; i < 8; i++)
#pragma unroll
                for (int j = 0; j < 8; j++) acc[i][j] = fmaf(regM[i], regN[j], acc[i][j]);
        }
        __syncthreads();
    }
#pragma unroll
    for (int half = 0; half < 2; half++) {
#pragma unroll
        for (int i = 0; i < 4; i++) {
            int row = blockM + half * 64 + tr * 4 + i;
            int ai = half * 4 + i;
            if (row < M) {
                float4 o0 = make_float4(acc[ai][0], acc[ai][1], acc[ai][2], acc[ai][3]);
                float4 o1 = make_float4(acc[ai][4], acc[ai][5], acc[ai][6], acc[ai][7]);
                *(float4*)(C + (long)row * 128 + tc * 4)      = o0;
                *(float4*)(C + (long)row * 128 + 64 + tc * 4) = o1;
            }
        }
    }
}

// ---------------- 9. SpMM (warp per dst row; deg_in = end-beg is free) ----------------
template <bool FINAL>
__global__ void __launch_bounds__(256) k_spmm(const float* __restrict__ bias,
                                              const void* __restrict__ gids) {
    int warp = (blockIdx.x * blockDim.x + threadIdx.x) >> 5;
    if (warp >= NNODES) return;
    int lane = threadIdx.x & 31;
    int beg = g_rowptr[warp], end = g_rowptr[warp + 1];
    const float* __restrict__ T = g_bufA;
    float4 acc0 = make_float4(0.f, 0.f, 0.f, 0.f);
    float4 acc1 = make_float4(0.f, 0.f, 0.f, 0.f);
    int e = beg;
    for (; e + 8 <= end; e += 8) {
        int s0 = g_csr[e],     s1 = g_csr[e + 1], s2 = g_csr[e + 2], s3 = g_csr[e + 3];
        int s4 = g_csr[e + 4], s5 = g_csr[e + 5], s6 = g_csr[e + 6], s7 = g_csr[e + 7];
        float4 v0 = __ldg((const float4*)(T + (long)s0 * 128 + lane * 4));
        float4 v1 = __ldg((const float4*)(T + (long)s1 * 128 + lane * 4));
        float4 v2 = __ldg((const float4*)(T + (long)s2 * 128 + lane * 4));
        float4 v3 = __ldg((const float4*)(T + (long)s3 * 128 + lane * 4));
        float4 v4 = __ldg((const float4*)(T + (long)s4 * 128 + lane * 4));
        float4 v5 = __ldg((const float4*)(T + (long)s5 * 128 + lane * 4));
        float4 v6 = __ldg((const float4*)(T + (long)s6 * 128 + lane * 4));
        float4 v7 = __ldg((const float4*)(T + (long)s7 * 128 + lane * 4));
        acc0.x += (v0.x + v1.x) + (v2.x + v3.x);
        acc0.y += (v0.y + v1.y) + (v2.y + v3.y);
        acc0.z += (v0.z + v1.z) + (v2.z + v3.z);
        acc0.w += (v0.w + v1.w) + (v2.w + v3.w);
        acc1.x += (v4.x + v5.x) + (v6.x + v7.x);
        acc1.y += (v4.y + v5.y) + (v6.y + v7.y);
        acc1.z += (v4.z + v5.z) + (v6.z + v7.z);
        acc1.w += (v4.w + v5.w) + (v6.w + v7.w);
    }
    for (; e + 4 <= end; e += 4) {
        int s0 = g_csr[e], s1 = g_csr[e + 1], s2 = g_csr[e + 2], s3 = g_csr[e + 3];
        float4 v0 = __ldg((const float4*)(T + (long)s0 * 128 + lane * 4));
        float4 v1 = __ldg((const float4*)(T + (long)s1 * 128 + lane * 4));
        float4 v2 = __ldg((const float4*)(T + (long)s2 * 128 + lane * 4));
        float4 v3 = __ldg((const float4*)(T + (long)s3 * 128 + lane * 4));
        acc0.x += (v0.x + v1.x) + (v2.x + v3.x);
        acc0.y += (v0.y + v1.y) + (v2.y + v3.y);
        acc0.z += (v0.z + v1.z) + (v2.z + v3.z);
        acc0.w += (v0.w + v1.w) + (v2.w + v3.w);
    }
    for (; e < end; e++) {
        int s = g_csr[e];
        float4 v = __ldg((const float4*)(T + (long)s * 128 + lane * 4));
        acc1.x += v.x; acc1.y += v.y; acc1.z += v.z; acc1.w += v.w;
    }
    float4 acc = make_float4(acc0.x + acc1.x, acc0.y + acc1.y,
                             acc0.z + acc1.z, acc0.w + acc1.w);
    float ri = rsqrtf((float)max(end - beg, 1));   // deg_in, free
    float4 b = *(const float4*)(bias + lane * 4);
    if (!FINAL) {
        float ro = rsqrtf((float)max(g_deg_out[warp], 1));
        float4 o;
        o.x = fmaxf(fmaf(acc.x, ri, b.x), 0.f) * ro;
        o.y = fmaxf(fmaf(acc.y, ri, b.y), 0.f) * ro;
        o.z = fmaxf(fmaf(acc.z, ri, b.z), 0.f) * ro;
        o.w = fmaxf(fmaf(acc.w, ri, b.w), 0.f) * ro;
        *(float4*)(g_bufB + (long)warp * 128 + lane * 4) = o;
    } else {
        float4 o;
        o.x = fmaxf(fmaf(acc.x, ri, b.x), 0.f);
        o.y = fmaxf(fmaf(acc.y, ri, b.y), 0.f);
        o.z = fmaxf(fmaf(acc.z, ri, b.z), 0.f);
        o.w = fmaxf(fmaf(acc.w, ri, b.w), 0.f);
        bool w64 = (g_idx64 != 0);
        int g = ldidx(gids, warp, w64);
        float* dstp = g_gsum + g * 128 + lane * 4;
        atomicAdd(dstp + 0, o.x);
        atomicAdd(dstp + 1, o.y);
        atomicAdd(dstp + 2, o.z);
        atomicAdd(dstp + 3, o.w);
    }
}

// ---------------- 10. classifier head: logits = (gsum/cnt) @ Wc + bc ----------------
__global__ void k_final(const float* __restrict__ Wc, const float* __restrict__ bc,
                        float* __restrict__ out) {
    int t = threadIdx.x;
    if (t >= NGRAPHS * NCLS) return;
    int g = t / NCLS, c = t % NCLS;
    float s = 0.f;
#pragma unroll 8
    for (int k = 0; k < 128; k++) s = fmaf(g_gsum[g * 128 + k], Wc[k * NCLS + c], s);
    float cnt = (float)max(g_gcnt[g], 1);
    out[t] = s / cnt + bc[c];
}

// ---------------- launch ----------------
extern "C" void kernel_launch(void* const* d_in, const int* in_sizes, int n_in,
                              void* d_out, int out_size) {
    const float* h   = (const float*)d_in[0];
    const void*  src = d_in[1];
    const void*  dst = d_in[2];
    const void*  gid = d_in[3];
    const float* W1  = (const float*)d_in[4];
    const float* b1  = (const float*)d_in[5];
    const float* W2  = (const float*)d_in[6];
    const float* b2  = (const float*)d_in[7];
    const float* Wc  = (const float*)d_in[8];
    const float* bc  = (const float*)d_in[9];
    float* out = (float*)d_out;

    const int M = NNODES;
    int gemmGrid = (M + 127) / 128;
    int spmmGrid = (M * 32 + 255) / 256;

    k_detect<<<1, 256>>>(src);                    // 1
    k_zero<<<512, 256>>>();                       // 2
    k_degrees<<<1184, 256>>>(src, dst, gid);      // 3
    k_sgemm<1><<<gemmGrid, 256>>>(h, W1, M);      // 4  <- profiled slot
    k_scanA<<<NBLK, SCAN_B>>>();                  // 5
    k_scanB<<<1, 128>>>();                        // 6
    k_scanC<<<NBLK, SCAN_B>>>();                  // 7
    k_scatter<<<1184, 256>>>(src, dst);           // 8
    k_spmm<false><<<spmmGrid, 256>>>(b1, nullptr);// 9
    k_sgemm<2><<<gemmGrid, 256>>>(nullptr, W2, M);// 10
    k_spmm<true><<<spmmGrid, 256>>>(b2, gid);     // 11
    k_final<<<1, NGRAPHS * NCLS>>>(Wc, bc, out);  // 12
}